// round 4
// baseline (speedup 1.0000x reference)
#include <cuda_runtime.h>

#define N_NODES 50000
#define N_EDGES 640000
#define D 128
#define C 64

// ---------------- device scratch (no allocation allowed) ----------------
__device__ float g_deg[N_NODES];
__device__ float g_dinv[N_NODES];
__device__ float g_h[(size_t)N_NODES * D];    // transformed features (h @ W)
__device__ float g_agg[(size_t)N_NODES * D];  // aggregated features

// ---------------- degree / normalization ----------------
__global__ void k_deg_init() {
    int i = blockIdx.x * blockDim.x + threadIdx.x;
    if (i < N_NODES) g_deg[i] = 1.0f;  // self-loop
}

__global__ void k_deg_count(const int* __restrict__ ei) {
    int e = blockIdx.x * blockDim.x + threadIdx.x;
    if (e < N_EDGES) {
        int d = ei[N_EDGES + e];  // dst row
        atomicAdd(&g_deg[d], 1.0f);
    }
}

__global__ void k_dinv() {
    int i = blockIdx.x * blockDim.x + threadIdx.x;
    if (i < N_NODES) g_dinv[i] = rsqrtf(g_deg[i]);
}

// ---------------- GEMM: out[N, DOUT] = relu?(in[N, D]) @ W[D, DOUT] (+bias) ----
// W resident in shared memory; block computes ROWS consecutive rows.
// blockDim.x == DOUT. ROWS must divide N_NODES.
template <int DOUT, int ROWS, bool RELU_IN>
__global__ void k_gemm(const float* __restrict__ in, const float* __restrict__ W,
                       const float* __restrict__ bias, float* __restrict__ out) {
    extern __shared__ float smem[];
    float* sW = smem;             // D * DOUT
    float* sx = smem + D * DOUT;  // ROWS * D
    const int tid = threadIdx.x;

    for (int i = tid; i < D * DOUT; i += DOUT) sW[i] = W[i];

    const int r0 = blockIdx.x * ROWS;
    for (int i = tid; i < ROWS * D; i += DOUT) {
        float v = in[(size_t)r0 * D + i];
        if (RELU_IN) v = fmaxf(v, 0.0f);
        sx[i] = v;
    }
    __syncthreads();

    const float binit = bias ? bias[tid] : 0.0f;

    for (int r = 0; r < ROWS; r += 2) {
        float a0 = binit, a1 = binit;
#pragma unroll 16
        for (int k = 0; k < D; k++) {
            float w = sW[k * DOUT + tid];
            a0 = fmaf(sx[r * D + k], w, a0);
            a1 = fmaf(sx[(r + 1) * D + k], w, a1);
        }
        out[(size_t)(r0 + r) * DOUT + tid] = a0;
        out[(size_t)(r0 + r + 1) * DOUT + tid] = a1;
    }
}

// ---------------- aggregation init: agg[i] = b + dinv[i]^2 * h[i] ------------
// (self-loop contribution + bias, non-atomic). Vectorized float4.
__global__ void k_agg_init(const float* __restrict__ h, const float* __restrict__ b,
                           float* __restrict__ agg) {
    int idx = blockIdx.x * blockDim.x + threadIdx.x;  // over N*D/4 float4s
    if (idx >= N_NODES * D / 4) return;
    int node = idx >> 5;       // 32 float4 per node
    int c4 = idx & 31;
    float di = g_dinv[node];
    float w = di * di;
    float4 hv = ((const float4*)h)[idx];
    float4 bv = ((const float4*)b)[c4];
    float4 o;
    o.x = fmaf(w, hv.x, bv.x);
    o.y = fmaf(w, hv.y, bv.y);
    o.z = fmaf(w, hv.z, bv.z);
    o.w = fmaf(w, hv.w, bv.w);
    ((float4*)agg)[idx] = o;
}

// ---------------- edge scatter: agg[dst] += norm * h[src] -------------------
// One warp per edge; lane handles one float4 (32 * 16B = 512B row).
__global__ void k_scatter(const int* __restrict__ ei, const float* __restrict__ h,
                          float* __restrict__ agg) {
    int w = (blockIdx.x * blockDim.x + threadIdx.x) >> 5;
    int lane = threadIdx.x & 31;
    if (w >= N_EDGES) return;
    int s = ei[w];
    int d = ei[N_EDGES + w];
    float wt = g_dinv[s] * g_dinv[d];
    float4 v = ((const float4*)(h + (size_t)s * D))[lane];
    float* ap = agg + (size_t)d * D + lane * 4;
    atomicAdd(ap + 0, v.x * wt);
    atomicAdd(ap + 1, v.y * wt);
    atomicAdd(ap + 2, v.z * wt);
    atomicAdd(ap + 3, v.w * wt);
}

// ---------------- launch ----------------
extern "C" void kernel_launch(void* const* d_in, const int* in_sizes, int n_in,
                              void* d_out, int out_size) {
    const float* x  = (const float*)d_in[0];
    const int* ei   = (const int*)d_in[1];
    const float* W1 = (const float*)d_in[2];
    const float* b1 = (const float*)d_in[3];
    const float* W2 = (const float*)d_in[4];
    const float* b2 = (const float*)d_in[5];
    const float* Wl = (const float*)d_in[6];
    const float* bl = (const float*)d_in[7];
    float* out = (float*)d_out;

    float *hbuf, *abuf;
    cudaGetSymbolAddress((void**)&hbuf, g_h);
    cudaGetSymbolAddress((void**)&abuf, g_agg);

    constexpr int ROWS = 16;
    const int gemm128_smem = (D * 128 + ROWS * D) * (int)sizeof(float);  // 72 KB
    const int gemm64_smem  = (D * 64 + ROWS * D) * (int)sizeof(float);   // 40 KB
    cudaFuncSetAttribute(k_gemm<128, ROWS, false>,
                         cudaFuncAttributeMaxDynamicSharedMemorySize, gemm128_smem);
    cudaFuncSetAttribute(k_gemm<128, ROWS, true>,
                         cudaFuncAttributeMaxDynamicSharedMemorySize, gemm128_smem);
    cudaFuncSetAttribute(k_gemm<64, ROWS, true>,
                         cudaFuncAttributeMaxDynamicSharedMemorySize, gemm64_smem);

    // degrees + symmetric norm
    k_deg_init<<<(N_NODES + 255) / 256, 256>>>();
    k_deg_count<<<(N_EDGES + 255) / 256, 256>>>(ei);
    k_dinv<<<(N_NODES + 255) / 256, 256>>>();

    const int n_vec4 = N_NODES * D / 4;
    const int scat_blocks = (N_EDGES * 32 + 255) / 256;

    // ----- layer 1: h = x @ W1; agg = b1 + D^-1/2 (A+I) D^-1/2 h -----
    k_gemm<128, ROWS, false><<<N_NODES / ROWS, 128, gemm128_smem>>>(x, W1, nullptr, hbuf);
    k_agg_init<<<(n_vec4 + 255) / 256, 256>>>(hbuf, b1, abuf);
    k_scatter<<<scat_blocks, 256>>>(ei, hbuf, abuf);

    // ----- layer 2: h = relu(agg) @ W2; aggregate again -----
    k_gemm<128, ROWS, true><<<N_NODES / ROWS, 128, gemm128_smem>>>(abuf, W2, nullptr, hbuf);
    k_agg_init<<<(n_vec4 + 255) / 256, 256>>>(hbuf, b2, abuf);
    k_scatter<<<scat_blocks, 256>>>(ei, hbuf, abuf);

    // ----- head: out = relu(agg) @ Wl + bl -----
    k_gemm<64, ROWS, true><<<N_NODES / ROWS, 64, gemm64_smem>>>(abuf, Wl, bl, out);
}

// round 5
// speedup vs baseline: 4.6691x; 4.6691x over previous
#include <cuda_runtime.h>

#define N_NODES 50000
#define N_EDGES 640000
#define D 128
#define C 64
#define SCAN_CHUNK 1024
#define SCAN_NBLK 49   // ceil(50000/1024)

// ---------------- device scratch (no allocation allowed) ----------------
__device__ int   g_cnt[N_NODES];        // in-degree (real edges only)
__device__ float g_dinv[N_NODES];       // rsqrt(deg+1)
__device__ int   g_rowptr[N_NODES + 1];
__device__ int   g_cursor[N_NODES];
__device__ int   g_blksum[64];
__device__ int   g_blkoff[64];
__device__ int   g_csr[N_EDGES];        // src indices grouped by dst
__device__ float g_h[(size_t)N_NODES * D];    // h' = dinv[i] * (in @ W)[i]
__device__ float g_agg[(size_t)N_NODES * D];  // aggregated features

// ---------------- degree / CSR build ----------------
__global__ void k_zero_cnt() {
    int i = blockIdx.x * blockDim.x + threadIdx.x;
    if (i < N_NODES) g_cnt[i] = 0;
}

__global__ void k_count(const int* __restrict__ ei) {
    int e = blockIdx.x * blockDim.x + threadIdx.x;
    if (e < N_EDGES) atomicAdd(&g_cnt[ei[N_EDGES + e]], 1);
}

__global__ void k_dinv() {
    int i = blockIdx.x * blockDim.x + threadIdx.x;
    if (i < N_NODES) g_dinv[i] = rsqrtf((float)(g_cnt[i] + 1));
}

// 3-phase exclusive scan of g_cnt -> g_rowptr
__global__ void k_scan1() {
    __shared__ int s[SCAN_CHUNK];
    int tid = threadIdx.x;
    int i = blockIdx.x * SCAN_CHUNK + tid;
    int v = (i < N_NODES) ? g_cnt[i] : 0;
    s[tid] = v;
    __syncthreads();
#pragma unroll
    for (int off = 1; off < SCAN_CHUNK; off <<= 1) {
        int t = (tid >= off) ? s[tid - off] : 0;
        __syncthreads();
        s[tid] += t;
        __syncthreads();
    }
    if (i < N_NODES) g_rowptr[i] = s[tid] - v;  // exclusive within block
    if (tid == SCAN_CHUNK - 1) g_blksum[blockIdx.x] = s[tid];
}

__global__ void k_scan2() {
    __shared__ int s[64];
    int tid = threadIdx.x;
    int v = (tid < SCAN_NBLK) ? g_blksum[tid] : 0;
    s[tid] = v;
    __syncthreads();
#pragma unroll
    for (int off = 1; off < 64; off <<= 1) {
        int t = (tid >= off) ? s[tid - off] : 0;
        __syncthreads();
        s[tid] += t;
        __syncthreads();
    }
    if (tid < SCAN_NBLK) g_blkoff[tid] = s[tid] - v;
}

__global__ void k_scan3() {
    int i = blockIdx.x * blockDim.x + threadIdx.x;
    if (i < N_NODES) {
        int p = g_rowptr[i] + g_blkoff[i / SCAN_CHUNK];
        g_rowptr[i] = p;
        g_cursor[i] = p;
    }
    if (i == 0) g_rowptr[N_NODES] = N_EDGES;
}

__global__ void k_fill(const int* __restrict__ ei) {
    int e = blockIdx.x * blockDim.x + threadIdx.x;
    if (e < N_EDGES) {
        int s = ei[e];
        int d = ei[N_EDGES + e];
        int pos = atomicAdd(&g_cursor[d], 1);
        g_csr[pos] = s;
    }
}

// ---------------- register-tiled GEMM ----------------
// out[row] = (dinv[row] if SCALE_OUT) * ( relu?(in[row]) @ W ) (+bias if ADD_BIAS)
// blockDim = 128. Thread tile 8 rows x 4 cols.
// DOUT=128: TILE_R=32 (NCC=32, one row-group per warp -> pure broadcast x loads)
// DOUT=64 : TILE_R=64 (NCC=16)
template <int DOUT, bool RELU_IN, bool SCALE_OUT, bool ADD_BIAS>
__global__ void k_gemm(const float* __restrict__ in, const float* __restrict__ W,
                       const float* __restrict__ bias, float* __restrict__ out) {
    constexpr int TILE_R = (DOUT == 128) ? 32 : 64;
    constexpr int NCC = DOUT / 4;
    extern __shared__ float smem[];
    float* sW = smem;               // D * DOUT
    float* sx = smem + D * DOUT;    // TILE_R * D
    const int tid = threadIdx.x;
    const int r0 = blockIdx.x * TILE_R;

    // load W (coalesced float4)
    {
        const float4* W4 = (const float4*)W;
        float4* sW4 = (float4*)sW;
        for (int i = tid; i < D * DOUT / 4; i += 128) sW4[i] = W4[i];
    }
    // load x tile (guarded, optional relu)
    {
        float4* sx4 = (float4*)sx;
        const float4* in4 = (const float4*)in;
        for (int i = tid; i < TILE_R * D / 4; i += 128) {
            int r = i / (D / 4);
            float4 v = make_float4(0.f, 0.f, 0.f, 0.f);
            if (r0 + r < N_NODES) {
                v = in4[(size_t)(r0 + r) * (D / 4) + (i % (D / 4))];
                if (RELU_IN) {
                    v.x = fmaxf(v.x, 0.f); v.y = fmaxf(v.y, 0.f);
                    v.z = fmaxf(v.z, 0.f); v.w = fmaxf(v.w, 0.f);
                }
            }
            sx4[i] = v;
        }
    }
    __syncthreads();

    const int cc = tid % NCC;
    const int rc = tid / NCC;  // 8 rows per group
    float acc[8][4];
#pragma unroll
    for (int r = 0; r < 8; r++)
#pragma unroll
        for (int c = 0; c < 4; c++) acc[r][c] = 0.f;

#pragma unroll 4
    for (int k = 0; k < D; k++) {
        float4 w = ((const float4*)(sW + k * DOUT))[cc];
#pragma unroll
        for (int r = 0; r < 8; r++) {
            float xv = sx[(rc * 8 + r) * D + k];
            acc[r][0] = fmaf(xv, w.x, acc[r][0]);
            acc[r][1] = fmaf(xv, w.y, acc[r][1]);
            acc[r][2] = fmaf(xv, w.z, acc[r][2]);
            acc[r][3] = fmaf(xv, w.w, acc[r][3]);
        }
    }

    float4 bv = make_float4(0.f, 0.f, 0.f, 0.f);
    if (ADD_BIAS) bv = ((const float4*)bias)[cc];

#pragma unroll
    for (int r = 0; r < 8; r++) {
        int row = r0 + rc * 8 + r;
        if (row < N_NODES) {
            float4 o = make_float4(acc[r][0], acc[r][1], acc[r][2], acc[r][3]);
            if (ADD_BIAS) { o.x += bv.x; o.y += bv.y; o.z += bv.z; o.w += bv.w; }
            if (SCALE_OUT) {
                float dv = g_dinv[row];
                o.x *= dv; o.y *= dv; o.z *= dv; o.w *= dv;
            }
            ((float4*)out)[(size_t)row * (DOUT / 4) + cc] = o;
        }
    }
}

// ---------------- CSR aggregation (atomic-free) --------------------------
// agg[d] = dinv[d] * ( sum_{s in N(d)} h'[s] + h'[d] ) + b
// One warp per node; lane owns one float4 (4 of 128 features).
__global__ void k_aggregate(const float* __restrict__ hp, const float* __restrict__ bias,
                            float* __restrict__ agg) {
    int d = (blockIdx.x * blockDim.x + threadIdx.x) >> 5;
    int lane = threadIdx.x & 31;
    if (d >= N_NODES) return;

    float4 acc = ((const float4*)(hp + (size_t)d * D))[lane];  // self term
    int beg = g_rowptr[d], end = g_rowptr[d + 1];

    for (int j = beg; j < end; j += 32) {
        int n = min(32, end - j);
        int s_l = (lane < n) ? g_csr[j + lane] : 0;
        int t = 0;
        for (; t + 4 <= n; t += 4) {
            int s0 = __shfl_sync(0xffffffffu, s_l, t);
            int s1 = __shfl_sync(0xffffffffu, s_l, t + 1);
            int s2 = __shfl_sync(0xffffffffu, s_l, t + 2);
            int s3 = __shfl_sync(0xffffffffu, s_l, t + 3);
            float4 v0 = ((const float4*)(hp + (size_t)s0 * D))[lane];
            float4 v1 = ((const float4*)(hp + (size_t)s1 * D))[lane];
            float4 v2 = ((const float4*)(hp + (size_t)s2 * D))[lane];
            float4 v3 = ((const float4*)(hp + (size_t)s3 * D))[lane];
            acc.x += (v0.x + v1.x) + (v2.x + v3.x);
            acc.y += (v0.y + v1.y) + (v2.y + v3.y);
            acc.z += (v0.z + v1.z) + (v2.z + v3.z);
            acc.w += (v0.w + v1.w) + (v2.w + v3.w);
        }
        for (; t < n; t++) {
            int s = __shfl_sync(0xffffffffu, s_l, t);
            float4 v = ((const float4*)(hp + (size_t)s * D))[lane];
            acc.x += v.x; acc.y += v.y; acc.z += v.z; acc.w += v.w;
        }
    }

    float dv = g_dinv[d];
    float4 bv = ((const float4*)bias)[lane];
    float4 o;
    o.x = fmaf(dv, acc.x, bv.x);
    o.y = fmaf(dv, acc.y, bv.y);
    o.z = fmaf(dv, acc.z, bv.z);
    o.w = fmaf(dv, acc.w, bv.w);
    ((float4*)(agg + (size_t)d * D))[lane] = o;
}

// ---------------- launch ----------------
extern "C" void kernel_launch(void* const* d_in, const int* in_sizes, int n_in,
                              void* d_out, int out_size) {
    const float* x  = (const float*)d_in[0];
    const int* ei   = (const int*)d_in[1];
    const float* W1 = (const float*)d_in[2];
    const float* b1 = (const float*)d_in[3];
    const float* W2 = (const float*)d_in[4];
    const float* b2 = (const float*)d_in[5];
    const float* Wl = (const float*)d_in[6];
    const float* bl = (const float*)d_in[7];
    float* out = (float*)d_out;

    float *hbuf, *abuf;
    cudaGetSymbolAddress((void**)&hbuf, g_h);
    cudaGetSymbolAddress((void**)&abuf, g_agg);

    const int gemm128_smem = (D * 128 + 32 * D) * (int)sizeof(float);  // 80 KB
    const int gemm64_smem  = (D * 64 + 64 * D) * (int)sizeof(float);   // 64 KB
    cudaFuncSetAttribute(k_gemm<128, false, true, false>,
                         cudaFuncAttributeMaxDynamicSharedMemorySize, gemm128_smem);
    cudaFuncSetAttribute(k_gemm<128, true, true, false>,
                         cudaFuncAttributeMaxDynamicSharedMemorySize, gemm128_smem);
    cudaFuncSetAttribute(k_gemm<64, true, false, true>,
                         cudaFuncAttributeMaxDynamicSharedMemorySize, gemm64_smem);

    // ---- graph prep: degrees, dinv, CSR ----
    k_zero_cnt<<<(N_NODES + 255) / 256, 256>>>();
    k_count<<<(N_EDGES + 255) / 256, 256>>>(ei);
    k_dinv<<<(N_NODES + 255) / 256, 256>>>();
    k_scan1<<<SCAN_NBLK, SCAN_CHUNK>>>();
    k_scan2<<<1, 64>>>();
    k_scan3<<<(N_NODES + 255) / 256, 256>>>();
    k_fill<<<(N_EDGES + 255) / 256, 256>>>(ei);

    const int g128 = (N_NODES + 31) / 32;
    const int g64  = (N_NODES + 63) / 64;
    const int gagg = (N_NODES * 32 + 255) / 256;

    // ----- layer 1 -----
    k_gemm<128, false, true, false><<<g128, 128, gemm128_smem>>>(x, W1, nullptr, hbuf);
    k_aggregate<<<gagg, 256>>>(hbuf, b1, abuf);

    // ----- layer 2 -----
    k_gemm<128, true, true, false><<<g128, 128, gemm128_smem>>>(abuf, W2, nullptr, hbuf);
    k_aggregate<<<gagg, 256>>>(hbuf, b2, abuf);

    // ----- head -----
    k_gemm<64, true, false, true><<<g64, 128, gemm64_smem>>>(abuf, Wl, bl, out);
}